// round 5
// baseline (speedup 1.0000x reference)
#include <cuda_runtime.h>

#define DMODEL 512
#define SEQ_T 2048
#define BATCH 4
#define NHEAD 8
#define HD 64
#define QKV_N (3 * DMODEL)

typedef unsigned long long ull;

// packed dual-fp32 ops (Blackwell f32x2) -------------------------------------
#define FMA_X2(acc, a, b) \
    asm("fma.rn.f32x2 %0, %1, %2, %0;" : "+l"(acc) : "l"(a), "l"(b))
#define MUL_X2(acc, b) \
    asm("mul.rn.f32x2 %0, %0, %1;" : "+l"(acc) : "l"(b))
#define ADD_X2(d, a, b) \
    asm("add.rn.f32x2 %0, %1, %2;" : "=l"(d) : "l"(a), "l"(b))
#define PACK2(d, lo, hi) \
    asm("mov.b64 %0, {%1, %2};" : "=l"(d) : "r"(__float_as_uint(lo)), "r"(__float_as_uint(hi)))
#define UNPACK2(lo, hi, s) \
    asm("mov.b64 {%0, %1}, %2;" : "=r"(lo), "=r"(hi) : "l"(s))

__device__ __forceinline__ float2 unpack2f(ull s) {
    unsigned int a, b;
    UNPACK2(a, b, s);
    return make_float2(__uint_as_float(a), __uint_as_float(b));
}
__device__ __forceinline__ ull pack_dup(float v) {
    ull d; PACK2(d, v, v); return d;
}

// Scratch (allocation-free rule: __device__ globals)
__device__ float g_qkv[(size_t)BATCH * SEQ_T * QKV_N];   // [B, T, 3*D]
__device__ float g_att[(size_t)BATCH * SEQ_T * DMODEL];  // [B, T, D]

// ---------------------------------------------------------------------------
// SGEMM: C[M,N] = A[M,K] @ B[K,N] + bias[N]
// 128x128 block tile, KT=8, 256 threads, 8x8 micro-tile via f32x2 FMAs.
// A smem tile stored DUPLICATED: As[kk][2r]=As[kk][2r+1]=A[r] so the
// per-row broadcast operand loads directly as (a,a) 64-bit pairs.
// Double-buffered smem: one __syncthreads per K-tile.
// ---------------------------------------------------------------------------
__global__ __launch_bounds__(256) void sgemm_bias(
    const float* __restrict__ A, const float* __restrict__ Bm,
    const float* __restrict__ bias, float* __restrict__ C,
    int M, int N, int K)
{
    __shared__ float As[2][8][256];
    __shared__ float Bs[2][8][128];

    const int tid = threadIdx.x;
    const int bm = blockIdx.y * 128;
    const int bn = blockIdx.x * 128;
    const int tx = tid & 15;   // 0..15
    const int ty = tid >> 4;   // 0..15

    ull acc[8][4];
#pragma unroll
    for (int i = 0; i < 8; i++)
#pragma unroll
        for (int j = 0; j < 4; j++) acc[i][j] = 0ull;

    // global load mapping
    const int a_row = tid >> 1;          // 0..127
    const int a_col = (tid & 1) * 4;     // 0 or 4
    const int b_row = tid >> 5;          // 0..7
    const int b_col = (tid & 31) * 4;    // 0..124

    const float* Ap = A + (size_t)(bm + a_row) * K + a_col;
    const float* Bp = Bm + (size_t)b_row * N + bn + b_col;

    // prologue: load tile 0 into buffer 0
    {
        float4 av = *(const float4*)(Ap);
        float4 bv = *(const float4*)(Bp);
        *(float2*)&As[0][a_col + 0][2 * a_row] = make_float2(av.x, av.x);
        *(float2*)&As[0][a_col + 1][2 * a_row] = make_float2(av.y, av.y);
        *(float2*)&As[0][a_col + 2][2 * a_row] = make_float2(av.z, av.z);
        *(float2*)&As[0][a_col + 3][2 * a_row] = make_float2(av.w, av.w);
        *(float4*)&Bs[0][b_row][b_col] = bv;
    }
    __syncthreads();

    int nb = 0;
    for (int k0 = 0; k0 < K; k0 += 8) {
        // prefetch next tile
        float4 av, bv;
        const bool more = (k0 + 8) < K;
        if (more) {
            av = *(const float4*)(Ap + k0 + 8);
            bv = *(const float4*)(Bp + (size_t)(k0 + 8) * N);
        }

        // compute on buffer nb
#pragma unroll
        for (int kk = 0; kk < 8; kk++) {
            ull a2[8], b2[4];
            {
                const longlong2 p0 = *(const longlong2*)&As[nb][kk][8 * ty];
                const longlong2 p1 = *(const longlong2*)&As[nb][kk][8 * ty + 4];
                const longlong2 p2 = *(const longlong2*)&As[nb][kk][128 + 8 * ty];
                const longlong2 p3 = *(const longlong2*)&As[nb][kk][128 + 8 * ty + 4];
                a2[0] = (ull)p0.x; a2[1] = (ull)p0.y;
                a2[2] = (ull)p1.x; a2[3] = (ull)p1.y;
                a2[4] = (ull)p2.x; a2[5] = (ull)p2.y;
                a2[6] = (ull)p3.x; a2[7] = (ull)p3.y;
            }
            {
                const longlong2 q0 = *(const longlong2*)&Bs[nb][kk][4 * tx];
                const longlong2 q1 = *(const longlong2*)&Bs[nb][kk][64 + 4 * tx];
                b2[0] = (ull)q0.x; b2[1] = (ull)q0.y;
                b2[2] = (ull)q1.x; b2[3] = (ull)q1.y;
            }
#pragma unroll
            for (int i = 0; i < 8; i++)
#pragma unroll
                for (int j = 0; j < 4; j++)
                    FMA_X2(acc[i][j], a2[i], b2[j]);
        }

        // store next tile into the other buffer
        if (more) {
            const int ob = nb ^ 1;
            *(float2*)&As[ob][a_col + 0][2 * a_row] = make_float2(av.x, av.x);
            *(float2*)&As[ob][a_col + 1][2 * a_row] = make_float2(av.y, av.y);
            *(float2*)&As[ob][a_col + 2][2 * a_row] = make_float2(av.z, av.z);
            *(float2*)&As[ob][a_col + 3][2 * a_row] = make_float2(av.w, av.w);
            *(float4*)&Bs[ob][b_row][b_col] = bv;
        }
        __syncthreads();
        nb ^= 1;
    }

    // epilogue
    float bl[8];
    *(float4*)(bl)     = *(const float4*)&bias[bn + tx * 4];
    *(float4*)(bl + 4) = *(const float4*)&bias[bn + 64 + tx * 4];
#pragma unroll
    for (int i = 0; i < 8; i++) {
        const int row = bm + ((i < 4) ? (ty * 4 + i) : (64 + ty * 4 + (i - 4)));
        float* crow = C + (size_t)row * N + bn;
        float2 p0 = unpack2f(acc[i][0]);
        float2 p1 = unpack2f(acc[i][1]);
        float4 o0;
        o0.x = p0.x + bl[0]; o0.y = p0.y + bl[1];
        o0.z = p1.x + bl[2]; o0.w = p1.y + bl[3];
        *(float4*)(crow + tx * 4) = o0;
        float2 p2 = unpack2f(acc[i][2]);
        float2 p3 = unpack2f(acc[i][3]);
        float4 o1;
        o1.x = p2.x + bl[4]; o1.y = p2.y + bl[5];
        o1.z = p3.x + bl[6]; o1.w = p3.y + bl[7];
        *(float4*)(crow + 64 + tx * 4) = o1;
    }
}

// ---------------------------------------------------------------------------
// Causal flash attention, fp32 math via f32x2 packed FMAs.
// One thread = one query row. Block = 128 threads = 128 query rows.
// K/V tiles (64 keys x 64 dims) staged in shared memory per (b,h).
// grid = (T/128, B*H); blockIdx.x reversed so heavy tiles schedule first.
// ---------------------------------------------------------------------------
__global__ __launch_bounds__(128) void attn_kernel(
    const float* __restrict__ qkv, float* __restrict__ att)
{
    const int bh = blockIdx.y;
    const int b = bh >> 3;        // NHEAD=8
    const int h = bh & 7;
    const int q0 = (gridDim.x - 1 - blockIdx.x) * 128;  // heavy blocks first
    const int tid = threadIdx.x;
    const int qi = q0 + tid;

    const float* base = qkv + (size_t)b * SEQ_T * QKV_N;

    // load + pre-scale q row (1/sqrt(64) = 0.125), packed as 32 f32x2 pairs
    ull q2[32];
    {
        const float4* qp = (const float4*)(base + (size_t)qi * QKV_N + h * HD);
#pragma unroll
        for (int i = 0; i < 16; i++) {
            float4 t = qp[i];
            t.x *= 0.125f; t.y *= 0.125f; t.z *= 0.125f; t.w *= 0.125f;
            PACK2(q2[2 * i],     t.x, t.y);
            PACK2(q2[2 * i + 1], t.z, t.w);
        }
    }

    float m = -1e30f, l = 0.f;
    ull acc[32];
#pragma unroll
    for (int i = 0; i < 32; i++) acc[i] = 0ull;

    __shared__ float Ks[64][64];
    __shared__ float Vs[64][64];

    const int kv_end = q0 + 128;   // keys needed by this block (exclusive)

    for (int j0 = 0; j0 < kv_end; j0 += 64) {
        __syncthreads();
        // cooperative load of K/V tile: 64 rows x 64 floats each
#pragma unroll
        for (int i = 0; i < 8; i++) {
            const int idx = tid + i * 128;        // 0..1023
            const int r = idx >> 4;
            const int c = (idx & 15) << 2;
            const float* krow = base + (size_t)(j0 + r) * QKV_N + DMODEL + h * HD + c;
            *(float4*)&Ks[r][c] = *(const float4*)krow;
            *(float4*)&Vs[r][c] = *(const float4*)(krow + DMODEL);
        }
        __syncthreads();

        int jmax = qi - j0 + 1;
        if (jmax > 64) jmax = 64;
        for (int j = 0; j < jmax; j++) {
            // score = q . k  (packed: 32 FFMA2 in 4 streams)
            ull sa = 0ull, sb = 0ull, sc = 0ull, sd = 0ull;
            const longlong2* kp = (const longlong2*)Ks[j];
#pragma unroll
            for (int i = 0; i < 8; i++) {
                longlong2 k01 = kp[2 * i];
                longlong2 k23 = kp[2 * i + 1];
                FMA_X2(sa, q2[4 * i + 0], (ull)k01.x);
                FMA_X2(sb, q2[4 * i + 1], (ull)k01.y);
                FMA_X2(sc, q2[4 * i + 2], (ull)k23.x);
                FMA_X2(sd, q2[4 * i + 3], (ull)k23.y);
            }
            ull se, sf2;
            ADD_X2(se, sa, sb);
            ADD_X2(sf2, sc, sd);
            ADD_X2(se, se, sf2);
            float2 sh = unpack2f(se);
            const float s = sh.x + sh.y;

            if (s > m) {   // rare: running max update + rescale
                const float corr = __expf(m - s);
                l *= corr;
                const ull c2 = pack_dup(corr);
#pragma unroll
                for (int d = 0; d < 32; d++) MUL_X2(acc[d], c2);
                m = s;
            }
            const float p = __expf(s - m);
            l += p;
            const ull p2 = pack_dup(p);

            const longlong2* vp = (const longlong2*)Vs[j];
#pragma unroll
            for (int i = 0; i < 16; i++) {
                longlong2 v = vp[i];
                FMA_X2(acc[2 * i + 0], p2, (ull)v.x);
                FMA_X2(acc[2 * i + 1], p2, (ull)v.y);
            }
        }
    }

    const float inv = 1.f / l;
    float* op = att + (size_t)(b * SEQ_T + qi) * DMODEL + h * HD;
#pragma unroll
    for (int i = 0; i < 16; i++) {
        float2 e0 = unpack2f(acc[2 * i + 0]);
        float2 e1 = unpack2f(acc[2 * i + 1]);
        float4 o;
        o.x = e0.x * inv; o.y = e0.y * inv;
        o.z = e1.x * inv; o.w = e1.y * inv;
        ((float4*)op)[i] = o;
    }
}

// ---------------------------------------------------------------------------
extern "C" void kernel_launch(void* const* d_in, const int* in_sizes, int n_in,
                              void* d_out, int out_size)
{
    (void)in_sizes; (void)n_in; (void)out_size;
    const float* x     = (const float*)d_in[0];
    const float* W_qkv = (const float*)d_in[1];
    const float* b_qkv = (const float*)d_in[2];
    const float* W_out = (const float*)d_in[3];
    const float* b_out = (const float*)d_in[4];
    float* out = (float*)d_out;

    float* qkvp = nullptr;
    float* attp = nullptr;
    cudaGetSymbolAddress((void**)&qkvp, g_qkv);
    cudaGetSymbolAddress((void**)&attp, g_att);

    const int M = BATCH * SEQ_T;   // 8192

    // 1) QKV projection: [8192,512] @ [512,1536] + b
    {
        dim3 grid(QKV_N / 128, M / 128);   // (12, 64)
        sgemm_bias<<<grid, 256>>>(x, W_qkv, b_qkv, qkvp, M, QKV_N, DMODEL);
    }
    // 2) causal flash attention
    {
        dim3 grid(SEQ_T / 128, BATCH * NHEAD);   // (16, 32)
        attn_kernel<<<grid, 128>>>(qkvp, attp);
    }
    // 3) output projection: [8192,512] @ [512,512] + b
    {
        dim3 grid(DMODEL / 128, M / 128);  // (4, 64)
        sgemm_bias<<<grid, 256>>>(attp, W_out, b_out, out, M, DMODEL, DMODEL);
    }
}

// round 10
// speedup vs baseline: 1.4299x; 1.4299x over previous
#include <cuda_runtime.h>
#include <cstdint>

#define DMODEL 512
#define SEQ_T 2048
#define BATCH 4
#define NHEAD 8
#define HD 64
#define QKV_N (3 * DMODEL)

// ===================== scratch (__device__ globals) ========================
__device__ float g_qkv[(size_t)BATCH * SEQ_T * QKV_N];   // [B, T, 3*D]
__device__ float g_att[(size_t)BATCH * SEQ_T * DMODEL];  // [B, T, D]
__device__ float g_wqkvT[(size_t)QKV_N * DMODEL];        // W_qkv^T [1536,512]
__device__ float g_woutT[(size_t)DMODEL * DMODEL];       // W_out^T [512,512]

// ======================= transpose: in[R,C] -> out[C,R] ====================
__global__ __launch_bounds__(256) void transpose_k(
    const float* __restrict__ in, float* __restrict__ out, int R, int C)
{
    __shared__ float t[32][33];
    const int c0 = blockIdx.x * 32, r0 = blockIdx.y * 32;
    const int x = threadIdx.x, y = threadIdx.y;  // 32 x 8
#pragma unroll
    for (int i = 0; i < 32; i += 8)
        t[y + i][x] = in[(size_t)(r0 + y + i) * C + c0 + x];
    __syncthreads();
#pragma unroll
    for (int i = 0; i < 32; i += 8)
        out[(size_t)(c0 + y + i) * R + r0 + x] = t[x][y + i];
}

// ===================== TF32 warp-MMA GEMM + bias ===========================
// C[M,N] = A[M,K] @ Bt[N,K]^T + bias[N]
// mma.sync.aligned.m16n8k8.row.col.f32.tf32.tf32.f32 (portable PTX, sm_80+)
// CTA: 128x128 tile, 256 threads = 8 warps (2 warp-rows x 4 warp-cols),
// warp tile 64x32 = 4x4 fragments. K-tile = 32.
// Smem tiles are stored FRAGMENT-PERMUTED so the hot loop reads each thread's
// A fragment with a single LDS.128 and B fragment with a single LDS.64.
//   A word index: ((mt*4+ks)*32 + t)*4 + reg   (mt 0..7, ks 0..3, t=lane, reg 0..3)
//   B word index: ((nt*4+ks)*32 + t)*2 + reg   (nt 0..15, ks 0..3, reg 0..1)
// ---------------------------------------------------------------------------
__device__ __forceinline__ uint32_t f2tf32(float v) {
    uint32_t r;
    asm("cvt.rna.tf32.f32 %0, %1;" : "=r"(r) : "f"(v));
    return r;
}

__device__ __forceinline__ void mma_tf32(float* c, const uint32_t* a, const uint32_t* b) {
    asm volatile(
        "mma.sync.aligned.m16n8k8.row.col.f32.tf32.tf32.f32 "
        "{%0,%1,%2,%3}, {%4,%5,%6,%7}, {%8,%9}, {%0,%1,%2,%3};"
        : "+f"(c[0]), "+f"(c[1]), "+f"(c[2]), "+f"(c[3])
        : "r"(a[0]), "r"(a[1]), "r"(a[2]), "r"(a[3]), "r"(b[0]), "r"(b[1]));
}

__global__ __launch_bounds__(256) void gemm_mma(
    const float* __restrict__ A, const float* __restrict__ Bt,
    const float* __restrict__ bias, float* __restrict__ C,
    int M, int N, int K)
{
    __shared__ uint32_t sA[4096];   // 128 rows x 32 k, fragment-permuted
    __shared__ uint32_t sB[4096];   // 128 n   x 32 k, fragment-permuted

    const int tid = threadIdx.x;
    const int lane = tid & 31;
    const int wid = tid >> 5;
    const int warp_m = wid >> 2;        // 0..1
    const int warp_n = wid & 3;         // 0..3
    const int bm = blockIdx.y * 128, bn = blockIdx.x * 128;

    float acc[4][4][4];                 // [mt][nt][reg]
#pragma unroll
    for (int i = 0; i < 4; i++)
#pragma unroll
        for (int j = 0; j < 4; j++)
#pragma unroll
            for (int r = 0; r < 4; r++) acc[i][j][r] = 0.f;

    const float* Agb = A + (size_t)bm * K;
    const float* Bgb = Bt + (size_t)bn * K;

    const int NT = K >> 5;

    // per-thread staging indices: 4 iterations, each a float4 of A and of B
    // idx = it*256 + tid; row = idx>>3 (0..127); c4 = idx&7 (float4 within 32-k row)
    float4 pa[4], pb[4];

    auto fetch = [&](int t) {
#pragma unroll
        for (int it = 0; it < 4; it++) {
            const int idx = it * 256 + tid;
            const int row = idx >> 3, c4 = idx & 7;
            pa[it] = *(const float4*)(Agb + (size_t)row * K + t * 32 + c4 * 4);
            pb[it] = *(const float4*)(Bgb + (size_t)row * K + t * 32 + c4 * 4);
        }
    };
    auto stage = [&]() {
#pragma unroll
        for (int it = 0; it < 4; it++) {
            const int idx = it * 256 + tid;
            const int row = idx >> 3, c4 = idx & 7;
            const int ks = c4 >> 1;
            {   // A: mt = row>>4, rr = row&15
                const int mt = row >> 4, rr = row & 15;
                const int reg = ((c4 & 1) << 1) | (rr >> 3);
                uint32_t base = (mt * 4 + ks) * 128 + ((rr & 7) << 4) + reg;
                sA[base + 0]  = f2tf32(pa[it].x);
                sA[base + 4]  = f2tf32(pa[it].y);
                sA[base + 8]  = f2tf32(pa[it].z);
                sA[base + 12] = f2tf32(pa[it].w);
            }
            {   // B: nt = row>>3, g = row&7
                const int nt = row >> 3, g = row & 7;
                const int reg = c4 & 1;
                uint32_t base = (nt * 4 + ks) * 64 + (g << 3) + reg;
                sB[base + 0] = f2tf32(pb[it].x);
                sB[base + 2] = f2tf32(pb[it].y);
                sB[base + 4] = f2tf32(pb[it].z);
                sB[base + 6] = f2tf32(pb[it].w);
            }
        }
    };

    fetch(0);
    stage();
    __syncthreads();

    for (int t = 0; t < NT; t++) {
        if (t + 1 < NT) fetch(t + 1);

#pragma unroll
        for (int ks = 0; ks < 4; ks++) {
            uint32_t af[4][4], bf[4][2];
#pragma unroll
            for (int mt = 0; mt < 4; mt++) {
                const uint32_t* p = &sA[((warp_m * 4 + mt) * 4 + ks) * 128 + lane * 4];
                uint4 v = *(const uint4*)p;
                af[mt][0] = v.x; af[mt][1] = v.y; af[mt][2] = v.z; af[mt][3] = v.w;
            }
#pragma unroll
            for (int nt = 0; nt < 4; nt++) {
                const uint32_t* p = &sB[((warp_n * 4 + nt) * 4 + ks) * 64 + lane * 2];
                uint2 v = *(const uint2*)p;
                bf[nt][0] = v.x; bf[nt][1] = v.y;
            }
#pragma unroll
            for (int mt = 0; mt < 4; mt++)
#pragma unroll
                for (int nt = 0; nt < 4; nt++)
                    mma_tf32(acc[mt][nt], af[mt], bf[nt]);
        }

        if (t + 1 < NT) {
            __syncthreads();
            stage();
            __syncthreads();
        }
    }

    // ---- epilogue: fragment -> gmem with bias ----
    const int g = lane >> 2, tq = lane & 3;
#pragma unroll
    for (int mt = 0; mt < 4; mt++) {
        const int row0 = bm + warp_m * 64 + mt * 16 + g;
#pragma unroll
        for (int nt = 0; nt < 4; nt++) {
            const int col = bn + warp_n * 32 + nt * 8 + tq * 2;
            const float b0 = bias[col], b1 = bias[col + 1];
            float2 o0 = make_float2(acc[mt][nt][0] + b0, acc[mt][nt][1] + b1);
            float2 o1 = make_float2(acc[mt][nt][2] + b0, acc[mt][nt][3] + b1);
            *(float2*)(C + (size_t)row0 * N + col) = o0;
            *(float2*)(C + (size_t)(row0 + 8) * N + col) = o1;
        }
    }
}

// ---------------------------------------------------------------------------
// Causal flash attention, fp32 (R1 version — proven fastest variant).
// One thread = one query row. Block = 128 threads = 128 query rows.
// grid = (T/128, B*H); blockIdx.x reversed so heavy tiles schedule first.
// ---------------------------------------------------------------------------
__global__ __launch_bounds__(128) void attn_kernel(
    const float* __restrict__ qkv, float* __restrict__ att)
{
    const int bh = blockIdx.y;
    const int b = bh >> 3;        // NHEAD=8
    const int h = bh & 7;
    const int q0 = (gridDim.x - 1 - blockIdx.x) * 128;
    const int tid = threadIdx.x;
    const int qi = q0 + tid;

    const float* base = qkv + (size_t)b * SEQ_T * QKV_N;

    float4 q[16];
    {
        const float4* qp = (const float4*)(base + (size_t)qi * QKV_N + h * HD);
#pragma unroll
        for (int i = 0; i < 16; i++) {
            float4 t = qp[i];
            t.x *= 0.125f; t.y *= 0.125f; t.z *= 0.125f; t.w *= 0.125f;
            q[i] = t;
        }
    }

    float m = -1e30f, l = 0.f;
    float acc[64];
#pragma unroll
    for (int i = 0; i < 64; i++) acc[i] = 0.f;

    __shared__ float Ks[64][64];
    __shared__ float Vs[64][64];

    const int kv_end = q0 + 128;

    for (int j0 = 0; j0 < kv_end; j0 += 64) {
        __syncthreads();
#pragma unroll
        for (int i = 0; i < 8; i++) {
            const int idx = tid + i * 128;
            const int r = idx >> 4;
            const int c = (idx & 15) << 2;
            const float* krow = base + (size_t)(j0 + r) * QKV_N + DMODEL + h * HD + c;
            *(float4*)&Ks[r][c] = *(const float4*)krow;
            *(float4*)&Vs[r][c] = *(const float4*)(krow + DMODEL);
        }
        __syncthreads();

        int jmax = qi - j0 + 1;
        if (jmax > 64) jmax = 64;
        for (int j = 0; j < jmax; j++) {
            const float4* kp = (const float4*)Ks[j];
            float s0 = 0.f, s1 = 0.f, s2 = 0.f, s3 = 0.f;
#pragma unroll
            for (int i = 0; i < 16; i += 4) {
                float4 k0 = kp[i], k1 = kp[i + 1], k2 = kp[i + 2], k3 = kp[i + 3];
                s0 += q[i].x * k0.x + q[i].y * k0.y + q[i].z * k0.z + q[i].w * k0.w;
                s1 += q[i + 1].x * k1.x + q[i + 1].y * k1.y + q[i + 1].z * k1.z + q[i + 1].w * k1.w;
                s2 += q[i + 2].x * k2.x + q[i + 2].y * k2.y + q[i + 2].z * k2.z + q[i + 2].w * k2.w;
                s3 += q[i + 3].x * k3.x + q[i + 3].y * k3.y + q[i + 3].z * k3.z + q[i + 3].w * k3.w;
            }
            const float s = (s0 + s1) + (s2 + s3);

            if (s > m) {
                const float corr = __expf(m - s);
                l *= corr;
#pragma unroll
                for (int d = 0; d < 64; d++) acc[d] *= corr;
                m = s;
            }
            const float p = __expf(s - m);
            l += p;

            const float4* vp = (const float4*)Vs[j];
#pragma unroll
            for (int i = 0; i < 16; i++) {
                float4 v = vp[i];
                acc[4 * i + 0] += p * v.x;
                acc[4 * i + 1] += p * v.y;
                acc[4 * i + 2] += p * v.z;
                acc[4 * i + 3] += p * v.w;
            }
        }
    }

    const float inv = 1.f / l;
    float* op = att + (size_t)(b * SEQ_T + qi) * DMODEL + h * HD;
#pragma unroll
    for (int i = 0; i < 16; i++) {
        float4 o;
        o.x = acc[4 * i + 0] * inv;
        o.y = acc[4 * i + 1] * inv;
        o.z = acc[4 * i + 2] * inv;
        o.w = acc[4 * i + 3] * inv;
        ((float4*)op)[i] = o;
    }
}

// ---------------------------------------------------------------------------
extern "C" void kernel_launch(void* const* d_in, const int* in_sizes, int n_in,
                              void* d_out, int out_size)
{
    (void)in_sizes; (void)n_in; (void)out_size;
    const float* x     = (const float*)d_in[0];
    const float* W_qkv = (const float*)d_in[1];
    const float* b_qkv = (const float*)d_in[2];
    const float* W_out = (const float*)d_in[3];
    const float* b_out = (const float*)d_in[4];
    float* out = (float*)d_out;

    float *qkvp = nullptr, *attp = nullptr, *wqkvT = nullptr, *woutT = nullptr;
    cudaGetSymbolAddress((void**)&qkvp, g_qkv);
    cudaGetSymbolAddress((void**)&attp, g_att);
    cudaGetSymbolAddress((void**)&wqkvT, g_wqkvT);
    cudaGetSymbolAddress((void**)&woutT, g_woutT);

    const int M = BATCH * SEQ_T;   // 8192

    // 0) transpose weights to K-major [N, K] (mma .row.col layout)
    {
        dim3 blk(32, 8);
        transpose_k<<<dim3(QKV_N / 32, DMODEL / 32), blk>>>(W_qkv, wqkvT, DMODEL, QKV_N);
        transpose_k<<<dim3(DMODEL / 32, DMODEL / 32), blk>>>(W_out, woutT, DMODEL, DMODEL);
    }
    // 1) QKV projection (tf32 warp MMA): [8192,512] @ [512,1536] + b
    {
        dim3 grid(QKV_N / 128, M / 128);   // (12, 64)
        gemm_mma<<<grid, 256>>>(x, wqkvT, b_qkv, qkvp, M, QKV_N, DMODEL);
    }
    // 2) causal flash attention
    {
        dim3 grid(SEQ_T / 128, BATCH * NHEAD);   // (16, 32)
        attn_kernel<<<grid, 128>>>(qkvp, attp);
    }
    // 3) output projection (tf32 warp MMA): [8192,512] @ [512,512] + b
    {
        dim3 grid(DMODEL / 128, M / 128);  // (4, 64)
        gemm_mma<<<grid, 256>>>(attp, woutT, b_out, out, M, DMODEL, DMODEL);
    }
}

// round 13
// speedup vs baseline: 2.8353x; 1.9829x over previous
#include <cuda_runtime.h>
#include <cstdint>

#define DMODEL 512
#define SEQ_T 2048
#define BATCH 4
#define NHEAD 8
#define HD 64
#define QKV_N (3 * DMODEL)

// ===================== scratch (__device__ globals) ========================
__device__ float g_qkv[(size_t)BATCH * SEQ_T * QKV_N];   // [B, T, 3*D]
__device__ float g_att[(size_t)BATCH * SEQ_T * DMODEL];  // [B, T, D]
__device__ float g_wqkvT[(size_t)QKV_N * DMODEL];        // W_qkv^T [1536,512]
__device__ float g_woutT[(size_t)DMODEL * DMODEL];       // W_out^T [512,512]

// ======================= helpers ==========================================
__device__ __forceinline__ uint32_t f2tf32(float v) {
    uint32_t r;
    asm("cvt.rna.tf32.f32 %0, %1;" : "=r"(r) : "f"(v));
    return r;
}
__device__ __forceinline__ void mma_tf32(float* c, const uint32_t* a, const uint32_t* b) {
    asm volatile(
        "mma.sync.aligned.m16n8k8.row.col.f32.tf32.tf32.f32 "
        "{%0,%1,%2,%3}, {%4,%5,%6,%7}, {%8,%9}, {%0,%1,%2,%3};"
        : "+f"(c[0]), "+f"(c[1]), "+f"(c[2]), "+f"(c[3])
        : "r"(a[0]), "r"(a[1]), "r"(a[2]), "r"(a[3]), "r"(b[0]), "r"(b[1]));
}

// ======================= transpose: in[R,C] -> out[C,R] ====================
__global__ __launch_bounds__(256) void transpose_k(
    const float* __restrict__ in, float* __restrict__ out, int R, int C)
{
    __shared__ float t[32][33];
    const int c0 = blockIdx.x * 32, r0 = blockIdx.y * 32;
    const int x = threadIdx.x, y = threadIdx.y;  // 32 x 8
#pragma unroll
    for (int i = 0; i < 32; i += 8)
        t[y + i][x] = in[(size_t)(r0 + y + i) * C + c0 + x];
    __syncthreads();
#pragma unroll
    for (int i = 0; i < 32; i += 8)
        out[(size_t)(c0 + y + i) * R + r0 + x] = t[x][y + i];
}

// ===================== TF32 warp-MMA GEMM + bias ===========================
// (verified passing in R10)
__global__ __launch_bounds__(256) void gemm_mma(
    const float* __restrict__ A, const float* __restrict__ Bt,
    const float* __restrict__ bias, float* __restrict__ C,
    int M, int N, int K)
{
    __shared__ uint32_t sA[4096];
    __shared__ uint32_t sB[4096];

    const int tid = threadIdx.x;
    const int lane = tid & 31;
    const int wid = tid >> 5;
    const int warp_m = wid >> 2;
    const int warp_n = wid & 3;
    const int bm = blockIdx.y * 128, bn = blockIdx.x * 128;

    float acc[4][4][4];
#pragma unroll
    for (int i = 0; i < 4; i++)
#pragma unroll
        for (int j = 0; j < 4; j++)
#pragma unroll
            for (int r = 0; r < 4; r++) acc[i][j][r] = 0.f;

    const float* Agb = A + (size_t)bm * K;
    const float* Bgb = Bt + (size_t)bn * K;
    const int NT = K >> 5;

    float4 pa[4], pb[4];
    auto fetch = [&](int t) {
#pragma unroll
        for (int it = 0; it < 4; it++) {
            const int idx = it * 256 + tid;
            const int row = idx >> 3, c4 = idx & 7;
            pa[it] = *(const float4*)(Agb + (size_t)row * K + t * 32 + c4 * 4);
            pb[it] = *(const float4*)(Bgb + (size_t)row * K + t * 32 + c4 * 4);
        }
    };
    auto stage = [&]() {
#pragma unroll
        for (int it = 0; it < 4; it++) {
            const int idx = it * 256 + tid;
            const int row = idx >> 3, c4 = idx & 7;
            const int ks = c4 >> 1;
            {
                const int mt = row >> 4, rr = row & 15;
                const int reg = ((c4 & 1) << 1) | (rr >> 3);
                uint32_t base = (mt * 4 + ks) * 128 + ((rr & 7) << 4) + reg;
                sA[base + 0]  = f2tf32(pa[it].x);
                sA[base + 4]  = f2tf32(pa[it].y);
                sA[base + 8]  = f2tf32(pa[it].z);
                sA[base + 12] = f2tf32(pa[it].w);
            }
            {
                const int nt = row >> 3, g = row & 7;
                const int reg = c4 & 1;
                uint32_t base = (nt * 4 + ks) * 64 + (g << 3) + reg;
                sB[base + 0] = f2tf32(pb[it].x);
                sB[base + 2] = f2tf32(pb[it].y);
                sB[base + 4] = f2tf32(pb[it].z);
                sB[base + 6] = f2tf32(pb[it].w);
            }
        }
    };

    fetch(0);
    stage();
    __syncthreads();

    for (int t = 0; t < NT; t++) {
        if (t + 1 < NT) fetch(t + 1);
#pragma unroll
        for (int ks = 0; ks < 4; ks++) {
            uint32_t af[4][4], bf[4][2];
#pragma unroll
            for (int mt = 0; mt < 4; mt++) {
                const uint32_t* p = &sA[((warp_m * 4 + mt) * 4 + ks) * 128 + lane * 4];
                uint4 v = *(const uint4*)p;
                af[mt][0] = v.x; af[mt][1] = v.y; af[mt][2] = v.z; af[mt][3] = v.w;
            }
#pragma unroll
            for (int nt = 0; nt < 4; nt++) {
                const uint32_t* p = &sB[((warp_n * 4 + nt) * 4 + ks) * 64 + lane * 2];
                uint2 v = *(const uint2*)p;
                bf[nt][0] = v.x; bf[nt][1] = v.y;
            }
#pragma unroll
            for (int mt = 0; mt < 4; mt++)
#pragma unroll
                for (int nt = 0; nt < 4; nt++)
                    mma_tf32(acc[mt][nt], af[mt], bf[nt]);
        }
        if (t + 1 < NT) {
            __syncthreads();
            stage();
            __syncthreads();
        }
    }

    const int g = lane >> 2, tq = lane & 3;
#pragma unroll
    for (int mt = 0; mt < 4; mt++) {
        const int row0 = bm + warp_m * 64 + mt * 16 + g;
#pragma unroll
        for (int nt = 0; nt < 4; nt++) {
            const int col = bn + warp_n * 32 + nt * 8 + tq * 2;
            const float b0 = bias[col], b1 = bias[col + 1];
            float2 o0 = make_float2(acc[mt][nt][0] + b0, acc[mt][nt][1] + b1);
            float2 o1 = make_float2(acc[mt][nt][2] + b0, acc[mt][nt][3] + b1);
            *(float2*)(C + (size_t)row0 * N + col) = o0;
            *(float2*)(C + (size_t)(row0 + 8) * N + col) = o1;
        }
    }
}

// ===================== tensor-core flash attention =========================
// CTA: one (b,h), 128 queries. 256 threads = 8 warps; warp w owns rows
// [q0+16w, q0+16w+15]. Key tiles of 64. All MMAs m16n8k8 tf32.
// smem (uint32 words): Qf[8192] Kf[4096] Vf[4096] Pf[8*1024]  = 96 KB
#define ATT_QF 0
#define ATT_KF 8192
#define ATT_VF 12288
#define ATT_PF 16384
#define ATT_SMEM_BYTES ((16384 + 8192) * 4)

__global__ __launch_bounds__(256) void attn_mma(
    const float* __restrict__ qkv, float* __restrict__ att)
{
    extern __shared__ uint32_t ash[];
    const int tid = threadIdx.x;
    const int lane = tid & 31;
    const int w = tid >> 5;            // warp 0..7  (= mt)
    const int g = lane >> 2, tq = lane & 3;

    const int bh = blockIdx.y;
    const int b = bh >> 3;
    const int h = bh & 7;
    const int q0 = (gridDim.x - 1 - blockIdx.x) * 128;   // heavy-first

    const float* base = qkv + (size_t)b * SEQ_T * QKV_N;

    // ---- stage Q once (A-fragment layout, pre-scaled) ----
#pragma unroll
    for (int it = 0; it < 8; it++) {
        const int idx = it * 256 + tid;
        const int row = idx >> 4, c4 = idx & 15;
        float4 qv = *(const float4*)(base + (size_t)(q0 + row) * QKV_N + h * HD + c4 * 4);
        qv.x *= 0.125f; qv.y *= 0.125f; qv.z *= 0.125f; qv.w *= 0.125f;
        const int mt = row >> 4, rr = row & 15;
        const int ks = c4 >> 1;
        const int reg = ((c4 & 1) << 1) | (rr >> 3);
        uint32_t sbase = ATT_QF + (mt * 8 + ks) * 128 + ((rr & 7) << 4) + reg;
        ash[sbase + 0]  = f2tf32(qv.x);
        ash[sbase + 4]  = f2tf32(qv.y);
        ash[sbase + 8]  = f2tf32(qv.z);
        ash[sbase + 12] = f2tf32(qv.w);
    }

    // softmax state: rows g (idx 0) and g+8 (idx 1)
    float m0 = -1e30f, m1 = -1e30f, l0 = 0.f, l1 = 0.f;
    float o[8][4];
#pragma unroll
    for (int i = 0; i < 8; i++)
#pragma unroll
        for (int r = 0; r < 4; r++) o[i][r] = 0.f;

    const int qi0 = q0 + w * 16 + g;
    const int qi1 = qi0 + 8;
    const int warp_row_max = q0 + w * 16 + 15;

    // P store offsets (A-frag layout): row g regs at +0, row g+8 at +1
    const int cc0 = 2 * tq, cc1 = 2 * tq + 1;
    const int offP0 = g * 16 + (cc0 & 3) * 4 + ((cc0 & 4) >> 1);
    const int offP1 = g * 16 + (cc1 & 3) * 4 + ((cc1 & 4) >> 1);
    uint32_t* Pw = &ash[ATT_PF + w * 1024];

    for (int j0 = 0; j0 < q0 + 128; j0 += 64) {
        __syncthreads();   // previous tile fully consumed
        // ---- stage K tile (B-frag layout: n=key, k=dim) ----
#pragma unroll
        for (int it = 0; it < 4; it++) {
            const int idx = it * 256 + tid;
            const int row = idx >> 4, c4 = idx & 15;   // row=key, c4=dim quad
            float4 kv = *(const float4*)(base + (size_t)(j0 + row) * QKV_N + DMODEL + h * HD + c4 * 4);
            const int nt = row >> 3, gg = row & 7;
            const int ks = c4 >> 1, reg = c4 & 1;
            uint32_t sbase = ATT_KF + (nt * 8 + ks) * 64 + gg * 8 + reg;
            ash[sbase + 0] = f2tf32(kv.x);
            ash[sbase + 2] = f2tf32(kv.y);
            ash[sbase + 4] = f2tf32(kv.z);
            ash[sbase + 6] = f2tf32(kv.w);
        }
        // ---- stage V tile transposed (B-frag layout: n=dim, k=key) ----
#pragma unroll
        for (int it = 0; it < 4; it++) {
            const int idx = it * 256 + tid;
            const int key = idx >> 4, c4 = idx & 15;   // c4 = dim quad
            float4 vv = *(const float4*)(base + (size_t)(j0 + key) * QKV_N + 2 * DMODEL + h * HD + c4 * 4);
            const int ks = key >> 3, kk = key & 7;
            const int reg = (kk >> 2) & 1, ii = kk & 3;
            const int d0 = c4 * 4;
            const uint32_t wb = ATT_VF + reg + 2 * ii;
            ash[wb + ((d0 >> 3) * 8 + ks) * 64 + (d0 & 7) * 8]             = f2tf32(vv.x);
            ash[wb + (((d0 + 1) >> 3) * 8 + ks) * 64 + ((d0 + 1) & 7) * 8] = f2tf32(vv.y);
            ash[wb + (((d0 + 2) >> 3) * 8 + ks) * 64 + ((d0 + 2) & 7) * 8] = f2tf32(vv.z);
            ash[wb + (((d0 + 3) >> 3) * 8 + ks) * 64 + ((d0 + 3) & 7) * 8] = f2tf32(vv.w);
        }
        __syncthreads();

        if (j0 > warp_row_max) continue;   // fully masked for this warp

        // ---- S = Q @ K^T ----
        float sf[8][4];
#pragma unroll
        for (int nt = 0; nt < 8; nt++)
#pragma unroll
            for (int r = 0; r < 4; r++) sf[nt][r] = 0.f;
#pragma unroll
        for (int ks = 0; ks < 8; ks++) {
            uint32_t af[4];
            uint4 av = *(const uint4*)&ash[ATT_QF + (w * 8 + ks) * 128 + lane * 4];
            af[0] = av.x; af[1] = av.y; af[2] = av.z; af[3] = av.w;
#pragma unroll
            for (int nt = 0; nt < 8; nt++) {
                uint2 bv = *(const uint2*)&ash[ATT_KF + (nt * 8 + ks) * 64 + lane * 2];
                uint32_t bf[2] = {bv.x, bv.y};
                mma_tf32(sf[nt], af, bf);
            }
        }

        // ---- causal mask (diagonal tiles only) ----
        if (j0 + 63 > qi0) {
#pragma unroll
            for (int nt = 0; nt < 8; nt++) {
                const int k0 = j0 + nt * 8 + cc0;
                if (k0 > qi0)     sf[nt][0] = -1e30f;
                if (k0 + 1 > qi0) sf[nt][1] = -1e30f;
                if (k0 > qi1)     sf[nt][2] = -1e30f;
                if (k0 + 1 > qi1) sf[nt][3] = -1e30f;
            }
        }

        // ---- online softmax ----
        float mx0 = -1e30f, mx1 = -1e30f;
#pragma unroll
        for (int nt = 0; nt < 8; nt++) {
            mx0 = fmaxf(mx0, fmaxf(sf[nt][0], sf[nt][1]));
            mx1 = fmaxf(mx1, fmaxf(sf[nt][2], sf[nt][3]));
        }
        mx0 = fmaxf(mx0, __shfl_xor_sync(0xffffffffu, mx0, 1));
        mx0 = fmaxf(mx0, __shfl_xor_sync(0xffffffffu, mx0, 2));
        mx1 = fmaxf(mx1, __shfl_xor_sync(0xffffffffu, mx1, 1));
        mx1 = fmaxf(mx1, __shfl_xor_sync(0xffffffffu, mx1, 2));

        const float nm0 = fmaxf(m0, mx0), nm1 = fmaxf(m1, mx1);
        const float cr0 = __expf(m0 - nm0), cr1 = __expf(m1 - nm1);
        m0 = nm0; m1 = nm1;
        l0 *= cr0; l1 *= cr1;
#pragma unroll
        for (int nt = 0; nt < 8; nt++) {
            o[nt][0] *= cr0; o[nt][1] *= cr0;
            o[nt][2] *= cr1; o[nt][3] *= cr1;
        }

        float ps0 = 0.f, ps1 = 0.f;
#pragma unroll
        for (int nt = 0; nt < 8; nt++) {
            const float p0 = __expf(sf[nt][0] - m0);
            const float p1 = __expf(sf[nt][1] - m0);
            const float p2 = __expf(sf[nt][2] - m1);
            const float p3 = __expf(sf[nt][3] - m1);
            ps0 += p0 + p1; ps1 += p2 + p3;
            uint32_t* pb = Pw + nt * 128;
            pb[offP0]     = f2tf32(p0);
            pb[offP1]     = f2tf32(p1);
            pb[offP0 + 1] = f2tf32(p2);
            pb[offP1 + 1] = f2tf32(p3);
        }
        l0 += ps0; l1 += ps1;

        // ---- O += P @ V ----
#pragma unroll
        for (int ks = 0; ks < 8; ks++) {
            uint32_t af[4];
            uint4 av = *(const uint4*)&Pw[ks * 128 + lane * 4];
            af[0] = av.x; af[1] = av.y; af[2] = av.z; af[3] = av.w;
#pragma unroll
            for (int nt = 0; nt < 8; nt++) {
                uint2 bv = *(const uint2*)&ash[ATT_VF + (nt * 8 + ks) * 64 + lane * 2];
                uint32_t bf[2] = {bv.x, bv.y};
                mma_tf32(o[nt], af, bf);
            }
        }
    }

    // ---- finalize: full row sums, normalize, store ----
    l0 += __shfl_xor_sync(0xffffffffu, l0, 1);
    l0 += __shfl_xor_sync(0xffffffffu, l0, 2);
    l1 += __shfl_xor_sync(0xffffffffu, l1, 1);
    l1 += __shfl_xor_sync(0xffffffffu, l1, 2);
    const float inv0 = 1.f / l0, inv1 = 1.f / l1;

    float* arow0 = att + (size_t)(b * SEQ_T + qi0) * DMODEL + h * HD;
    float* arow1 = att + (size_t)(b * SEQ_T + qi1) * DMODEL + h * HD;
#pragma unroll
    for (int nt = 0; nt < 8; nt++) {
        const int col = nt * 8 + cc0;
        *(float2*)(arow0 + col) = make_float2(o[nt][0] * inv0, o[nt][1] * inv0);
        *(float2*)(arow1 + col) = make_float2(o[nt][2] * inv1, o[nt][3] * inv1);
    }
}

// ---------------------------------------------------------------------------
extern "C" void kernel_launch(void* const* d_in, const int* in_sizes, int n_in,
                              void* d_out, int out_size)
{
    (void)in_sizes; (void)n_in; (void)out_size;
    const float* x     = (const float*)d_in[0];
    const float* W_qkv = (const float*)d_in[1];
    const float* b_qkv = (const float*)d_in[2];
    const float* W_out = (const float*)d_in[3];
    const float* b_out = (const float*)d_in[4];
    float* out = (float*)d_out;

    float *qkvp = nullptr, *attp = nullptr, *wqkvT = nullptr, *woutT = nullptr;
    cudaGetSymbolAddress((void**)&qkvp, g_qkv);
    cudaGetSymbolAddress((void**)&attp, g_att);
    cudaGetSymbolAddress((void**)&wqkvT, g_wqkvT);
    cudaGetSymbolAddress((void**)&woutT, g_woutT);

    cudaFuncSetAttribute(attn_mma, cudaFuncAttributeMaxDynamicSharedMemorySize, ATT_SMEM_BYTES);

    const int M = BATCH * SEQ_T;   // 8192

    // 0) transpose weights to K-major [N, K]
    {
        dim3 blk(32, 8);
        transpose_k<<<dim3(QKV_N / 32, DMODEL / 32), blk>>>(W_qkv, wqkvT, DMODEL, QKV_N);
        transpose_k<<<dim3(DMODEL / 32, DMODEL / 32), blk>>>(W_out, woutT, DMODEL, DMODEL);
    }
    // 1) QKV projection
    {
        dim3 grid(QKV_N / 128, M / 128);
        gemm_mma<<<grid, 256>>>(x, wqkvT, b_qkv, qkvp, M, QKV_N, DMODEL);
    }
    // 2) causal flash attention (tensor cores)
    {
        dim3 grid(SEQ_T / 128, BATCH * NHEAD);
        attn_mma<<<grid, 256, ATT_SMEM_BYTES>>>(qkvp, attp);
    }
    // 3) output projection
    {
        dim3 grid(DMODEL / 128, M / 128);
        gemm_mma<<<grid, 256>>>(attp, woutT, b_out, out, M, DMODEL, DMODEL);
    }
}

// round 14
// speedup vs baseline: 3.4666x; 1.2227x over previous
#include <cuda_runtime.h>
#include <cstdint>

#define DMODEL 512
#define SEQ_T 2048
#define BATCH 4
#define NHEAD 8
#define HD 64
#define QKV_N (3 * DMODEL)

// ===================== scratch (__device__ globals) ========================
__device__ float g_qkv[(size_t)BATCH * SEQ_T * QKV_N];   // [B, T, 3*D]
__device__ float g_att[(size_t)BATCH * SEQ_T * DMODEL];  // [B, T, D]
__device__ float g_wqkvT[(size_t)QKV_N * DMODEL];        // W_qkv^T [1536,512]
__device__ float g_woutT[(size_t)DMODEL * DMODEL];       // W_out^T [512,512]

// ======================= helpers ==========================================
__device__ __forceinline__ uint32_t f2tf32(float v) {
    uint32_t r;
    asm("cvt.rna.tf32.f32 %0, %1;" : "=r"(r) : "f"(v));
    return r;
}
__device__ __forceinline__ void mma_tf32(float* c, const uint32_t* a, const uint32_t* b) {
    asm volatile(
        "mma.sync.aligned.m16n8k8.row.col.f32.tf32.tf32.f32 "
        "{%0,%1,%2,%3}, {%4,%5,%6,%7}, {%8,%9}, {%0,%1,%2,%3};"
        : "+f"(c[0]), "+f"(c[1]), "+f"(c[2]), "+f"(c[3])
        : "r"(a[0]), "r"(a[1]), "r"(a[2]), "r"(a[3]), "r"(b[0]), "r"(b[1]));
}

// ======================= transpose: in[R,C] -> out[C,R] ====================
__global__ __launch_bounds__(256) void transpose_k(
    const float* __restrict__ in, float* __restrict__ out, int R, int C)
{
    __shared__ float t[32][33];
    const int c0 = blockIdx.x * 32, r0 = blockIdx.y * 32;
    const int x = threadIdx.x, y = threadIdx.y;  // 32 x 8
#pragma unroll
    for (int i = 0; i < 32; i += 8)
        t[y + i][x] = in[(size_t)(r0 + y + i) * C + c0 + x];
    __syncthreads();
#pragma unroll
    for (int i = 0; i < 32; i += 8)
        out[(size_t)(c0 + y + i) * R + r0 + x] = t[x][y + i];
}

// ===================== TF32 warp-MMA GEMM + bias ===========================
// (verified passing in R10/R13)
__global__ __launch_bounds__(256) void gemm_mma(
    const float* __restrict__ A, const float* __restrict__ Bt,
    const float* __restrict__ bias, float* __restrict__ C,
    int M, int N, int K)
{
    __shared__ uint32_t sA[4096];
    __shared__ uint32_t sB[4096];

    const int tid = threadIdx.x;
    const int lane = tid & 31;
    const int wid = tid >> 5;
    const int warp_m = wid >> 2;
    const int warp_n = wid & 3;
    const int bm = blockIdx.y * 128, bn = blockIdx.x * 128;

    float acc[4][4][4];
#pragma unroll
    for (int i = 0; i < 4; i++)
#pragma unroll
        for (int j = 0; j < 4; j++)
#pragma unroll
            for (int r = 0; r < 4; r++) acc[i][j][r] = 0.f;

    const float* Agb = A + (size_t)bm * K;
    const float* Bgb = Bt + (size_t)bn * K;
    const int NT = K >> 5;

    float4 pa[4], pb[4];
    auto fetch = [&](int t) {
#pragma unroll
        for (int it = 0; it < 4; it++) {
            const int idx = it * 256 + tid;
            const int row = idx >> 3, c4 = idx & 7;
            pa[it] = *(const float4*)(Agb + (size_t)row * K + t * 32 + c4 * 4);
            pb[it] = *(const float4*)(Bgb + (size_t)row * K + t * 32 + c4 * 4);
        }
    };
    auto stage = [&]() {
#pragma unroll
        for (int it = 0; it < 4; it++) {
            const int idx = it * 256 + tid;
            const int row = idx >> 3, c4 = idx & 7;
            const int ks = c4 >> 1;
            {
                const int mt = row >> 4, rr = row & 15;
                const int reg = ((c4 & 1) << 1) | (rr >> 3);
                uint32_t base = (mt * 4 + ks) * 128 + ((rr & 7) << 4) + reg;
                sA[base + 0]  = f2tf32(pa[it].x);
                sA[base + 4]  = f2tf32(pa[it].y);
                sA[base + 8]  = f2tf32(pa[it].z);
                sA[base + 12] = f2tf32(pa[it].w);
            }
            {
                const int nt = row >> 3, g = row & 7;
                const int reg = c4 & 1;
                uint32_t base = (nt * 4 + ks) * 64 + (g << 3) + reg;
                sB[base + 0] = f2tf32(pb[it].x);
                sB[base + 2] = f2tf32(pb[it].y);
                sB[base + 4] = f2tf32(pb[it].z);
                sB[base + 6] = f2tf32(pb[it].w);
            }
        }
    };

    fetch(0);
    stage();
    __syncthreads();

    for (int t = 0; t < NT; t++) {
        if (t + 1 < NT) fetch(t + 1);
#pragma unroll
        for (int ks = 0; ks < 4; ks++) {
            uint32_t af[4][4], bf[4][2];
#pragma unroll
            for (int mt = 0; mt < 4; mt++) {
                const uint32_t* p = &sA[((warp_m * 4 + mt) * 4 + ks) * 128 + lane * 4];
                uint4 v = *(const uint4*)p;
                af[mt][0] = v.x; af[mt][1] = v.y; af[mt][2] = v.z; af[mt][3] = v.w;
            }
#pragma unroll
            for (int nt = 0; nt < 4; nt++) {
                const uint32_t* p = &sB[((warp_n * 4 + nt) * 4 + ks) * 64 + lane * 2];
                uint2 v = *(const uint2*)p;
                bf[nt][0] = v.x; bf[nt][1] = v.y;
            }
#pragma unroll
            for (int mt = 0; mt < 4; mt++)
#pragma unroll
                for (int nt = 0; nt < 4; nt++)
                    mma_tf32(acc[mt][nt], af[mt], bf[nt]);
        }
        if (t + 1 < NT) {
            __syncthreads();
            stage();
            __syncthreads();
        }
    }

    const int g = lane >> 2, tq = lane & 3;
#pragma unroll
    for (int mt = 0; mt < 4; mt++) {
        const int row0 = bm + warp_m * 64 + mt * 16 + g;
#pragma unroll
        for (int nt = 0; nt < 4; nt++) {
            const int col = bn + warp_n * 32 + nt * 8 + tq * 2;
            const float b0 = bias[col], b1 = bias[col + 1];
            float2 o0 = make_float2(acc[mt][nt][0] + b0, acc[mt][nt][1] + b1);
            float2 o1 = make_float2(acc[mt][nt][2] + b0, acc[mt][nt][3] + b1);
            *(float2*)(C + (size_t)row0 * N + col) = o0;
            *(float2*)(C + (size_t)(row0 + 8) * N + col) = o1;
        }
    }
}

// ===================== tensor-core flash attention =========================
// CTA: one (b,h), 128 queries, 8 warps x 16 rows, 64-key tiles, tf32 MMAs.
// K/V smem tiles XOR-swizzled for conflict-free staging stores; next tile's
// K/V prefetched into registers during the PV phase (sf regs dead there).
// smem words: Qf[8192] Kf[4096] Vf[4096] Pf[8*1024] = 96 KB
#define ATT_QF 0
#define ATT_KF 8192
#define ATT_VF 12288
#define ATT_PF 16384
#define ATT_SMEM_BYTES ((16384 + 8192) * 4)
#define LOG2E 1.4426950408889634f

__global__ __launch_bounds__(256, 2) void attn_mma(
    const float* __restrict__ qkv, float* __restrict__ att)
{
    extern __shared__ uint32_t ash[];
    const int tid = threadIdx.x;
    const int lane = tid & 31;
    const int w = tid >> 5;            // warp 0..7  (= mt)
    const int g = lane >> 2, tq = lane & 3;

    const int bh = blockIdx.y;
    const int b = bh >> 3;
    const int h = bh & 7;
    const int q0 = (gridDim.x - 1 - blockIdx.x) * 128;   // heavy-first

    const float* base = qkv + (size_t)b * SEQ_T * QKV_N;

    // ---- stage Q once (A-fragment layout, pre-scaled into log2 domain) ----
    const float qscale = 0.125f * LOG2E;
#pragma unroll
    for (int it = 0; it < 8; it++) {
        const int idx = it * 256 + tid;
        const int row = idx >> 4, c4 = idx & 15;
        float4 qv = *(const float4*)(base + (size_t)(q0 + row) * QKV_N + h * HD + c4 * 4);
        qv.x *= qscale; qv.y *= qscale; qv.z *= qscale; qv.w *= qscale;
        const int mt = row >> 4, rr = row & 15;
        const int ks = c4 >> 1;
        const int reg = ((c4 & 1) << 1) | (rr >> 3);
        uint32_t sbase = ATT_QF + (mt * 8 + ks) * 128 + ((rr & 7) << 4) + reg;
        ash[sbase + 0]  = f2tf32(qv.x);
        ash[sbase + 4]  = f2tf32(qv.y);
        ash[sbase + 8]  = f2tf32(qv.z);
        ash[sbase + 12] = f2tf32(qv.w);
    }

    // softmax state (log2 domain): rows g (idx 0) and g+8 (idx 1)
    float m0 = -1e30f, m1 = -1e30f, l0 = 0.f, l1 = 0.f;
    float o[8][4];
#pragma unroll
    for (int i = 0; i < 8; i++)
#pragma unroll
        for (int r = 0; r < 4; r++) o[i][r] = 0.f;

    const int qi0 = q0 + w * 16 + g;
    const int qi1 = qi0 + 8;
    const int warp_row_max = q0 + w * 16 + 15;

    // P store offsets (A-frag layout); rows g / g+8 are adjacent words -> STS.64
    const int cc0 = 2 * tq, cc1 = 2 * tq + 1;
    const int offP0 = g * 16 + (cc0 & 3) * 4 + ((cc0 & 4) >> 1);
    const int offP1 = g * 16 + (cc1 & 3) * 4 + ((cc1 & 4) >> 1);
    uint32_t* Pw = &ash[ATT_PF + w * 1024];

    // per-lane swizzle constants for K/V fragment loads
    const uint32_t kswz = ((lane >> 2) & 1) << 1;   // key&1 on load side
    const uint32_t vswz = (uint32_t)(lane & 16);    // ((dim&4)<<2) on load side

    // ---- K/V prefetch registers ----
    float4 kf[4], vf[4];
    auto fetch_tile = [&](int j0n) {
#pragma unroll
        for (int it = 0; it < 4; it++) {
            const int idx = it * 256 + tid;
            const int row = idx >> 4, c4 = idx & 15;
            const float* kp = base + (size_t)(j0n + row) * QKV_N + DMODEL + h * HD + c4 * 4;
            kf[it] = *(const float4*)kp;
            vf[it] = *(const float4*)(kp + DMODEL);
        }
    };
    auto stage_tile = [&]() {
#pragma unroll
        for (int it = 0; it < 4; it++) {
            const int idx = it * 256 + tid;
            const int row = idx >> 4, c4 = idx & 15;
            {   // K: B-frag layout (n=key, k=dim), swizzled
                const int nt = row >> 3, gg = row & 7;
                const int ks = c4 >> 1, reg = c4 & 1;
                const uint32_t kb = ATT_KF + (nt * 8 + ks) * 64;
                const uint32_t sw = (uint32_t)((ks << 2) ^ ((gg & 1) << 1));
                ash[kb + ((uint32_t)(gg * 8 + 0 + reg) ^ sw)] = f2tf32(kf[it].x);
                ash[kb + ((uint32_t)(gg * 8 + 2 + reg) ^ sw)] = f2tf32(kf[it].y);
                ash[kb + ((uint32_t)(gg * 8 + 4 + reg) ^ sw)] = f2tf32(kf[it].z);
                ash[kb + ((uint32_t)(gg * 8 + 6 + reg) ^ sw)] = f2tf32(kf[it].w);
            }
            {   // V transposed: B-frag layout (n=dim, k=key), swizzled
                const int key = row;
                const int ks = key >> 3, kk = key & 7;
                const int reg = kk >> 2, ii = kk & 3;
                const int d0 = c4 * 4;
                const float vv[4] = {vf[it].x, vf[it].y, vf[it].z, vf[it].w};
#pragma unroll
                for (int e = 0; e < 4; e++) {
                    const int d = d0 + e;
                    const int nt = d >> 3, gg = d & 7;
                    const uint32_t vb = ATT_VF + (nt * 8 + ks) * 64;
                    const uint32_t low = (uint32_t)(gg * 8 + 2 * ii + reg)
                                       ^ (uint32_t)((nt << 1) ^ ((gg & 4) << 2));
                    ash[vb + low] = f2tf32(vv[e]);
                }
            }
        }
    };

    fetch_tile(0);
    const int ntiles = (q0 + 128) >> 6;

    for (int t = 0; t < ntiles; t++) {
        const int j0 = t << 6;
        __syncthreads();            // previous tile fully consumed
        stage_tile();
        __syncthreads();            // tile t staged

        const bool active = (j0 <= warp_row_max);

        if (active) {
            // ---- S = Q @ K^T ----
            float sf[8][4];
#pragma unroll
            for (int nt = 0; nt < 8; nt++)
#pragma unroll
                for (int r = 0; r < 4; r++) sf[nt][r] = 0.f;
#pragma unroll
            for (int ks = 0; ks < 8; ks++) {
                uint32_t af[4];
                uint4 av = *(const uint4*)&ash[ATT_QF + (w * 8 + ks) * 128 + lane * 4];
                af[0] = av.x; af[1] = av.y; af[2] = av.z; af[3] = av.w;
#pragma unroll
                for (int nt = 0; nt < 8; nt++) {
                    uint2 bv = *(const uint2*)&ash[ATT_KF + (nt * 8 + ks) * 64
                                   + (((uint32_t)(lane * 2)) ^ (uint32_t)(ks << 2) ^ kswz)];
                    uint32_t bf[2] = {bv.x, bv.y};
                    mma_tf32(sf[nt], af, bf);
                }
            }

            // ---- causal mask (diagonal tiles only) ----
            if (j0 + 63 > qi0) {
#pragma unroll
                for (int nt = 0; nt < 8; nt++) {
                    const int k0 = j0 + nt * 8 + cc0;
                    if (k0 > qi0)     sf[nt][0] = -1e30f;
                    if (k0 + 1 > qi0) sf[nt][1] = -1e30f;
                    if (k0 > qi1)     sf[nt][2] = -1e30f;
                    if (k0 + 1 > qi1) sf[nt][3] = -1e30f;
                }
            }

            // ---- online softmax (log2 domain) ----
            float mx0 = -1e30f, mx1 = -1e30f;
#pragma unroll
            for (int nt = 0; nt < 8; nt++) {
                mx0 = fmaxf(mx0, fmaxf(sf[nt][0], sf[nt][1]));
                mx1 = fmaxf(mx1, fmaxf(sf[nt][2], sf[nt][3]));
            }
            mx0 = fmaxf(mx0, __shfl_xor_sync(0xffffffffu, mx0, 1));
            mx0 = fmaxf(mx0, __shfl_xor_sync(0xffffffffu, mx0, 2));
            mx1 = fmaxf(mx1, __shfl_xor_sync(0xffffffffu, mx1, 1));
            mx1 = fmaxf(mx1, __shfl_xor_sync(0xffffffffu, mx1, 2));

            const float nm0 = fmaxf(m0, mx0), nm1 = fmaxf(m1, mx1);
            const float cr0 = exp2f(m0 - nm0), cr1 = exp2f(m1 - nm1);
            m0 = nm0; m1 = nm1;
            l0 *= cr0; l1 *= cr1;
#pragma unroll
            for (int nt = 0; nt < 8; nt++) {
                o[nt][0] *= cr0; o[nt][1] *= cr0;
                o[nt][2] *= cr1; o[nt][3] *= cr1;
            }

            float ps0 = 0.f, ps1 = 0.f;
#pragma unroll
            for (int nt = 0; nt < 8; nt++) {
                const float p0 = exp2f(sf[nt][0] - m0);
                const float p1 = exp2f(sf[nt][1] - m0);
                const float p2 = exp2f(sf[nt][2] - m1);
                const float p3 = exp2f(sf[nt][3] - m1);
                ps0 += p0 + p1; ps1 += p2 + p3;
                uint32_t* pb = Pw + nt * 128;
                *(uint2*)&pb[offP0] = make_uint2(f2tf32(p0), f2tf32(p2));
                *(uint2*)&pb[offP1] = make_uint2(f2tf32(p1), f2tf32(p3));
            }
            l0 += ps0; l1 += ps1;
        }

        // prefetch next tile's K/V during PV (sf regs are dead here)
        if (t + 1 < ntiles) fetch_tile((t + 1) << 6);

        if (active) {
            // ---- O += P @ V ----
#pragma unroll
            for (int ks = 0; ks < 8; ks++) {
                uint32_t af[4];
                uint4 av = *(const uint4*)&Pw[ks * 128 + lane * 4];
                af[0] = av.x; af[1] = av.y; af[2] = av.z; af[3] = av.w;
#pragma unroll
                for (int nt = 0; nt < 8; nt++) {
                    uint2 bv = *(const uint2*)&ash[ATT_VF + (nt * 8 + ks) * 64
                                   + (((uint32_t)(lane * 2)) ^ (uint32_t)(nt << 1) ^ vswz)];
                    uint32_t bf[2] = {bv.x, bv.y};
                    mma_tf32(o[nt], af, bf);
                }
            }
        }
    }

    // ---- finalize ----
    l0 += __shfl_xor_sync(0xffffffffu, l0, 1);
    l0 += __shfl_xor_sync(0xffffffffu, l0, 2);
    l1 += __shfl_xor_sync(0xffffffffu, l1, 1);
    l1 += __shfl_xor_sync(0xffffffffu, l1, 2);
    const float inv0 = 1.f / l0, inv1 = 1.f / l1;

    float* arow0 = att + (size_t)(b * SEQ_T + qi0) * DMODEL + h * HD;
    float* arow1 = att + (size_t)(b * SEQ_T + qi1) * DMODEL + h * HD;
#pragma unroll
    for (int nt = 0; nt < 8; nt++) {
        const int col = nt * 8 + cc0;
        *(float2*)(arow0 + col) = make_float2(o[nt][0] * inv0, o[nt][1] * inv0);
        *(float2*)(arow1 + col) = make_float2(o[nt][2] * inv1, o[nt][3] * inv1);
    }
}

// ---------------------------------------------------------------------------
extern "C" void kernel_launch(void* const* d_in, const int* in_sizes, int n_in,
                              void* d_out, int out_size)
{
    (void)in_sizes; (void)n_in; (void)out_size;
    const float* x     = (const float*)d_in[0];
    const float* W_qkv = (const float*)d_in[1];
    const float* b_qkv = (const float*)d_in[2];
    const float* W_out = (const float*)d_in[3];
    const float* b_out = (const float*)d_in[4];
    float* out = (float*)d_out;

    float *qkvp = nullptr, *attp = nullptr, *wqkvT = nullptr, *woutT = nullptr;
    cudaGetSymbolAddress((void**)&qkvp, g_qkv);
    cudaGetSymbolAddress((void**)&attp, g_att);
    cudaGetSymbolAddress((void**)&wqkvT, g_wqkvT);
    cudaGetSymbolAddress((void**)&woutT, g_woutT);

    cudaFuncSetAttribute(attn_mma, cudaFuncAttributeMaxDynamicSharedMemorySize, ATT_SMEM_BYTES);

    const int M = BATCH * SEQ_T;   // 8192

    // 0) transpose weights to K-major [N, K]
    {
        dim3 blk(32, 8);
        transpose_k<<<dim3(QKV_N / 32, DMODEL / 32), blk>>>(W_qkv, wqkvT, DMODEL, QKV_N);
        transpose_k<<<dim3(DMODEL / 32, DMODEL / 32), blk>>>(W_out, woutT, DMODEL, DMODEL);
    }
    // 1) QKV projection
    {
        dim3 grid(QKV_N / 128, M / 128);
        gemm_mma<<<grid, 256>>>(x, wqkvT, b_qkv, qkvp, M, QKV_N, DMODEL);
    }
    // 2) causal flash attention (tensor cores)
    {
        dim3 grid(SEQ_T / 128, BATCH * NHEAD);
        attn_mma<<<grid, 256, ATT_SMEM_BYTES>>>(qkvp, attp);
    }
    // 3) output projection
    {
        dim3 grid(DMODEL / 128, M / 128);
        gemm_mma<<<grid, 256>>>(attp, woutT, b_out, out, M, DMODEL, DMODEL);
    }
}